// round 11
// baseline (speedup 1.0000x reference)
#include <cuda_runtime.h>

#define TE 16
#define NODES_MAX 50000

typedef unsigned long long ull;

__device__ float g_agg_s[(size_t)NODES_MAX * 64];
__device__ float g_agg_v[(size_t)NODES_MAX * 192];

__device__ __forceinline__ ull ffma2(ull a, ull b, ull c) {
  ull d;
  asm("fma.rn.f32x2 %0, %1, %2, %3;" : "=l"(d) : "l"(a), "l"(b), "l"(c));
  return d;
}
__device__ __forceinline__ ull pack2(float x) {
  ull d;
  asm("mov.b64 %0, {%1, %1};" : "=l"(d) : "f"(x));
  return d;
}
__device__ __forceinline__ void upk16(const ull* a, float* f) {
#pragma unroll
  for (int j = 0; j < 8; j++) {
    f[2 * j]     = __int_as_float((int)(unsigned)(a[j] & 0xffffffffull));
    f[2 * j + 1] = __int_as_float((int)(unsigned)(a[j] >> 32));
  }
}
__device__ __forceinline__ float sigm(float x) { return 1.0f / (1.0f + __expf(-x)); }

#define RSQRT3 0.5773502692f
#define INV1   0.0622573010f   // 1/sqrt(258)
#define INV2   0.0883883476f   // 1/sqrt(128)
#define INV0   0.0625f         // 1/sqrt(256)
#define INVU   0.0883883476f   // 1/sqrt(128)

// one smem row (16 edges, 4x LDS.128 broadcast) feeds TWO output columns
#define ACC8W2(arrRow, wa, wb, A, B) do {                                      \
    ulonglong2 _r0 = *reinterpret_cast<const ulonglong2*>(arrRow);             \
    ulonglong2 _r1 = *reinterpret_cast<const ulonglong2*>((arrRow) + 4);       \
    ulonglong2 _r2 = *reinterpret_cast<const ulonglong2*>((arrRow) + 8);       \
    ulonglong2 _r3 = *reinterpret_cast<const ulonglong2*>((arrRow) + 12);      \
    (A)[0] = ffma2(_r0.x, (wa), (A)[0]);  (B)[0] = ffma2(_r0.x, (wb), (B)[0]); \
    (A)[1] = ffma2(_r0.y, (wa), (A)[1]);  (B)[1] = ffma2(_r0.y, (wb), (B)[1]); \
    (A)[2] = ffma2(_r1.x, (wa), (A)[2]);  (B)[2] = ffma2(_r1.x, (wb), (B)[2]); \
    (A)[3] = ffma2(_r1.y, (wa), (A)[3]);  (B)[3] = ffma2(_r1.y, (wb), (B)[3]); \
    (A)[4] = ffma2(_r2.x, (wa), (A)[4]);  (B)[4] = ffma2(_r2.x, (wb), (B)[4]); \
    (A)[5] = ffma2(_r2.y, (wa), (A)[5]);  (B)[5] = ffma2(_r2.y, (wb), (B)[5]); \
    (A)[6] = ffma2(_r3.x, (wa), (A)[6]);  (B)[6] = ffma2(_r3.x, (wb), (B)[6]); \
    (A)[7] = ffma2(_r3.y, (wa), (A)[7]);  (B)[7] = ffma2(_r3.y, (wb), (B)[7]); \
  } while (0)

// R=2 GEMM over 16 edges: thread owns outputs (2*o2, 2*o2+1); one LDG.64 per k.
// MLP=4 weight batching; K multiple of 4; compile-time strides only.
template <int K, int LDW, int RS>
__device__ __forceinline__ void gemmR2(const float* __restrict__ W, int o2,
                                       const float* __restrict__ row,
                                       ull* accA, ull* accB) {
#pragma unroll 1
  for (int k0 = 0; k0 < K; k0 += 4) {
    float2 w[4];
#pragma unroll
    for (int j = 0; j < 4; j++)
      w[j] = __ldg(reinterpret_cast<const float2*>(W + (size_t)(k0 + j) * LDW) + o2);
#pragma unroll
    for (int j = 0; j < 4; j++) {
      ull wa = pack2(w[j].x), wb = pack2(w[j].y);
      ACC8W2(row + (size_t)(k0 + j) * RS, wa, wb, accA, accB);
    }
  }
}

// ---------------------------------------------------------------------------
// Edge kernel: 16 edges/CTA, 128 threads, dynamic smem 70.1 KB (3 CTAs/SM).
// Role structure identical to R9 (proven): split scalar GEMM, 4-role vector.
// ---------------------------------------------------------------------------
#define EOFF_XS   0       // [130][16]
#define EOFF_D1   2080    // [128][16]; m2-scalar exchange
#define EOFF_XV   4128    // [128*3][16]
#define EOFF_MS   10272   // [64][16]
#define EOFF_G    11296   // [64][16]
#define EOFF_D2   12320   // [64][16]
#define EOFF_MV   13344   // [64*3][16]; m1-scalar exchange
#define EOFF_P    16416   // [64][16]
#define EOFF_ASX  17440
#define EOFF_AVX  17456   // [3][16]
#define EOFF_SND  17504
#define EOFF_RCV  17520
#define EDGE_SMEM_BYTES (17536 * 4)

__global__ void __launch_bounds__(128) edge_kernel(
    const float* __restrict__ node_s, const float* __restrict__ node_v,
    const float* __restrict__ eas, const float* __restrict__ eav,
    const float* __restrict__ add_feat,
    const float* __restrict__ Wss1, const float* __restrict__ Wvs1,
    const float* __restrict__ Wsv1, const float* __restrict__ Wvv1,
    const float* __restrict__ b1,
    const float* __restrict__ Wss2, const float* __restrict__ Wvs2,
    const float* __restrict__ Wsv2, const float* __restrict__ Wvv2,
    const float* __restrict__ b2,
    const int* __restrict__ senders, const int* __restrict__ receivers,
    int E)
{
  extern __shared__ __align__(16) float sm[];
  float* xs_rT = sm + EOFF_XS;
  float* d1T   = sm + EOFF_D1;
  float* xvT   = sm + EOFF_XV;
  float* ms_rT = sm + EOFF_MS;
  float* gT    = sm + EOFF_G;
  float* d2T   = sm + EOFF_D2;
  float* mvT   = sm + EOFF_MV;
  float* pT    = sm + EOFF_P;
  float* asx   = sm + EOFF_ASX;
  float* avx   = sm + EOFF_AVX;
  int* sndx = (int*)(sm + EOFF_SND);
  int* rcvx = (int*)(sm + EOFF_RCV);

  const int tid = threadIdx.x;
  const int e0 = blockIdx.x * TE;

  if (tid < TE) {
    int ge = e0 + tid;
    bool val = ge < E;
    sndx[tid] = val ? senders[ge] : 0;
    rcvx[tid] = val ? receivers[ge] : -1;
    asx[tid]  = val ? eas[ge] : 0.f;
#pragma unroll
    for (int i = 0; i < 3; i++) avx[i * 16 + tid] = val ? eav[ge * 3 + i] : 0.f;
  }
  __syncthreads();

  for (int idx = tid; idx < TE * 130; idx += 128) {
    int e = idx / 130, s = idx - e * 130;
    int r = rcvx[e] < 0 ? 0 : rcvx[e];
    float v;
    if (s < 64)       v = __ldg(node_s + (size_t)sndx[e] * 64 + s);
    else if (s < 128) v = __ldg(node_s + (size_t)r * 64 + (s - 64));
    else {
      int ge = e0 + e;
      v = (ge < E) ? __ldg(add_feat + (size_t)ge * 2 + (s - 128)) : 0.f;
    }
    xs_rT[s * 16 + e] = v;
  }
  for (int idx = tid; idx < TE * 384; idx += 128) {
    int e = idx / 384, j = idx - e * 384;
    int r = rcvx[e] < 0 ? 0 : rcvx[e];
    float v = (j < 192) ? __ldg(node_v + (size_t)sndx[e] * 192 + j)
                        : __ldg(node_v + (size_t)r * 192 + (j - 192));
    xvT[j * 16 + e] = v;
  }
  __syncthreads();

  for (int t = tid; t < TE * 128; t += 128) {
    int v = t >> 4, e = t & 15;
    d1T[v * 16 + e] = (xvT[(v * 3 + 0) * 16 + e] * avx[e] +
                       xvT[(v * 3 + 1) * 16 + e] * avx[16 + e] +
                       xvT[(v * 3 + 2) * 16 + e] * avx[32 + e]) * RSQRT3;
  }
  __syncthreads();

  // ---- m1 scalar: grp0 = xs@Wss1, grp1 = d1@Wvs1 -> exchange (mvT) ----
  {
    const int grp = tid >> 6;
    const int o2 = tid & 63;
    float* exch = mvT;
    ull accA[8] = {0,0,0,0,0,0,0,0}, accB[8] = {0,0,0,0,0,0,0,0};
    if (grp == 0) {
      gemmR2<128, 128, 16>(Wss1, o2, xs_rT, accA, accB);
      float2 w0 = __ldg(reinterpret_cast<const float2*>(Wss1 + (size_t)128 * 128) + o2);
      float2 w1 = __ldg(reinterpret_cast<const float2*>(Wss1 + (size_t)129 * 128) + o2);
      ACC8W2(xs_rT + 128 * 16, pack2(w0.x), pack2(w0.y), accA, accB);
      ACC8W2(xs_rT + 129 * 16, pack2(w1.x), pack2(w1.y), accA, accB);
    } else {
      gemmR2<128, 128, 16>(Wvs1, o2, d1T, accA, accB);
      float pa[16], pb[16]; upk16(accA, pa); upk16(accB, pb);
#pragma unroll
      for (int e = 0; e < TE; e++) {
        exch[(2 * o2) * 16 + e] = pa[e];
        exch[(2 * o2 + 1) * 16 + e] = pb[e];
      }
    }
    __syncthreads();
    if (grp == 0) {
      float pa[16], pb[16]; upk16(accA, pa); upk16(accB, pb);
      int oA = 2 * o2, oB = 2 * o2 + 1;
      float bA = __ldg(b1 + oA), bB = __ldg(b1 + oB);
      if (oA < 64) {
#pragma unroll
        for (int e = 0; e < TE; e++) {
          float a = asx[e];
          float s1 = (a * pa[e] + exch[oA * 16 + e]) * INV1 + bA;
          ms_rT[oA * 16 + e] = s1 * sigm(s1);
          float s2 = (a * pb[e] + exch[oB * 16 + e]) * INV1 + bB;
          ms_rT[oB * 16 + e] = s2 * sigm(s2);
        }
      } else {
#pragma unroll
        for (int e = 0; e < TE; e++) {
          float a = asx[e];
          gT[(oA - 64) * 16 + e] = sigm((a * pa[e] + exch[oA * 16 + e]) * INV1 + bA);
          gT[(oB - 64) * 16 + e] = sigm((a * pb[e] + exch[oB * 16 + e]) * INV1 + bB);
        }
      }
    }
  }
  __syncthreads();

  // ---- m1 vector: 4 roles x 32 threads x output pair ----
  {
    const int role = tid >> 5;
    const int o2 = tid & 31;
    ull accA[8] = {0,0,0,0,0,0,0,0}, accB[8] = {0,0,0,0,0,0,0,0};
    if (role < 3) {
      gemmR2<128, 64, 48>(Wvv1, o2, xvT + role * 16, accA, accB);
    } else {
      gemmR2<128, 64, 16>(Wsv1, o2, xs_rT, accA, accB);
      float2 w0 = __ldg(reinterpret_cast<const float2*>(Wsv1 + (size_t)128 * 64) + o2);
      float2 w1 = __ldg(reinterpret_cast<const float2*>(Wsv1 + (size_t)129 * 64) + o2);
      ACC8W2(xs_rT + 128 * 16, pack2(w0.x), pack2(w0.y), accA, accB);
      ACC8W2(xs_rT + 129 * 16, pack2(w1.x), pack2(w1.y), accA, accB);
      float pa[16], pb[16]; upk16(accA, pa); upk16(accB, pb);
#pragma unroll
      for (int e = 0; e < TE; e++) {
        pT[(2 * o2) * 16 + e] = pa[e];
        pT[(2 * o2 + 1) * 16 + e] = pb[e];
      }
    }
    __syncthreads();
    if (role < 3) {
      float qa[16], qb[16]; upk16(accA, qa); upk16(accB, qb);
      int oA = 2 * o2, oB = 2 * o2 + 1;
#pragma unroll
      for (int e = 0; e < TE; e++) {
        float a = asx[e];
        mvT[(oA * 3 + role) * 16 + e] =
            (pT[oA * 16 + e] * avx[role * 16 + e] + a * qa[e]) * gT[oA * 16 + e] * INV1;
        mvT[(oB * 3 + role) * 16 + e] =
            (pT[oB * 16 + e] * avx[role * 16 + e] + a * qb[e]) * gT[oB * 16 + e] * INV1;
      }
    }
  }
  __syncthreads();

  for (int t = tid; t < TE * 64; t += 128) {
    int v = t >> 4, e = t & 15;
    d2T[v * 16 + e] = (mvT[(v * 3 + 0) * 16 + e] * avx[e] +
                       mvT[(v * 3 + 1) * 16 + e] * avx[16 + e] +
                       mvT[(v * 3 + 2) * 16 + e] * avx[32 + e]) * RSQRT3;
  }
  __syncthreads();

  // ---- m2 scalar: grp0 = ms@Wss2, grp1 = d2@Wvs2 -> exchange (d1T) ----
  {
    const int grp = tid >> 6;
    const int o2 = tid & 63;
    float* exch = d1T;
    ull accA[8] = {0,0,0,0,0,0,0,0}, accB[8] = {0,0,0,0,0,0,0,0};
    if (grp == 0) {
      gemmR2<64, 128, 16>(Wss2, o2, ms_rT, accA, accB);
    } else {
      gemmR2<64, 128, 16>(Wvs2, o2, d2T, accA, accB);
      float pa[16], pb[16]; upk16(accA, pa); upk16(accB, pb);
#pragma unroll
      for (int e = 0; e < TE; e++) {
        exch[(2 * o2) * 16 + e] = pa[e];
        exch[(2 * o2 + 1) * 16 + e] = pb[e];
      }
    }
    __syncthreads();
    if (grp == 0) {
      float pa[16], pb[16]; upk16(accA, pa); upk16(accB, pb);
      int oA = 2 * o2, oB = 2 * o2 + 1;
      float bA = __ldg(b2 + oA), bB = __ldg(b2 + oB);
      if (oA < 64) {
#pragma unroll
        for (int e = 0; e < TE; e++) {
          int r = rcvx[e];
          if (r < 0) continue;
          float a = asx[e];
          float s1 = (a * pa[e] + exch[oA * 16 + e]) * INV2 + bA;
          float s2 = (a * pb[e] + exch[oB * 16 + e]) * INV2 + bB;
          atomicAdd(g_agg_s + (size_t)r * 64 + oA, s1 * sigm(s1));
          atomicAdd(g_agg_s + (size_t)r * 64 + oB, s2 * sigm(s2));
        }
      } else {
#pragma unroll
        for (int e = 0; e < TE; e++) {
          float a = asx[e];
          gT[(oA - 64) * 16 + e] = sigm((a * pa[e] + exch[oA * 16 + e]) * INV2 + bA);
          gT[(oB - 64) * 16 + e] = sigm((a * pb[e] + exch[oB * 16 + e]) * INV2 + bB);
        }
      }
    }
  }
  __syncthreads();

  // ---- m2 vector: 4 roles x 32 x pair; atomic scatter ----
  {
    const int role = tid >> 5;
    const int o2 = tid & 31;
    ull accA[8] = {0,0,0,0,0,0,0,0}, accB[8] = {0,0,0,0,0,0,0,0};
    if (role < 3) {
      gemmR2<64, 64, 48>(Wvv2, o2, mvT + role * 16, accA, accB);
    } else {
      gemmR2<64, 64, 16>(Wsv2, o2, ms_rT, accA, accB);
      float pa[16], pb[16]; upk16(accA, pa); upk16(accB, pb);
#pragma unroll
      for (int e = 0; e < TE; e++) {
        pT[(2 * o2) * 16 + e] = pa[e];
        pT[(2 * o2 + 1) * 16 + e] = pb[e];
      }
    }
    __syncthreads();
    if (role < 3) {
      float qa[16], qb[16]; upk16(accA, qa); upk16(accB, qb);
      int oA = 2 * o2, oB = 2 * o2 + 1;
#pragma unroll
      for (int e = 0; e < TE; e++) {
        int r = rcvx[e];
        if (r < 0) continue;
        float a = asx[e];
        atomicAdd(g_agg_v + (size_t)r * 192 + oA * 3 + role,
                  (pT[oA * 16 + e] * avx[role * 16 + e] + a * qa[e]) * gT[oA * 16 + e] * INV2);
        atomicAdd(g_agg_v + (size_t)r * 192 + oB * 3 + role,
                  (pT[oB * 16 + e] * avx[role * 16 + e] + a * qb[e]) * gT[oB * 16 + e] * INV2);
      }
    }
  }
}

// ---------------------------------------------------------------------------
// Node kernel: 16 nodes/CTA, same structure, dynamic smem 69.9 KB.
// ---------------------------------------------------------------------------
#define NOFF_XS   0       // [128][16]
#define NOFF_D1   2048
#define NOFF_XV   4096    // [128*3][16]
#define NOFF_HS   10240
#define NOFF_G    11264   // u1-scalar exchange
#define NOFF_D2   12288
#define NOFF_HV   13312   // [64*3][16]; u0-scalar exchange
#define NOFF_P    16384
#define NOFF_ASX  17408
#define NOFF_AVX  17424
#define NODE_SMEM_BYTES (17472 * 4)

__global__ void __launch_bounds__(128) node_kernel(
    const float* __restrict__ node_s, const float* __restrict__ node_v,
    const float* __restrict__ nas, const float* __restrict__ nav,
    const float* __restrict__ Wss0, const float* __restrict__ Wvs0,
    const float* __restrict__ Wsv0, const float* __restrict__ Wvv0,
    const float* __restrict__ b0,
    const float* __restrict__ Wssu, const float* __restrict__ Wvsu,
    const float* __restrict__ Wsvu, const float* __restrict__ Wvvu,
    const float* __restrict__ bu,
    float* __restrict__ out, int N)
{
  extern __shared__ __align__(16) float sm[];
  float* xs_rT = sm + NOFF_XS;
  float* d1T   = sm + NOFF_D1;
  float* xvT   = sm + NOFF_XV;
  float* hs_rT = sm + NOFF_HS;
  float* gT    = sm + NOFF_G;
  float* d2T   = sm + NOFF_D2;
  float* hvT   = sm + NOFF_HV;
  float* pT    = sm + NOFF_P;
  float* asx   = sm + NOFF_ASX;
  float* avx   = sm + NOFF_AVX;

  const int tid = threadIdx.x;
  const int n0 = blockIdx.x * TE;

  if (tid < TE) {
    int n = n0 + tid;
    bool val = n < N;
    asx[tid] = val ? nas[n] : 0.f;
#pragma unroll
    for (int i = 0; i < 3; i++) avx[i * 16 + tid] = val ? nav[n * 3 + i] : 0.f;
  }
  __syncthreads();

  for (int idx = tid; idx < TE * 128; idx += 128) {
    int e = idx >> 7, s = idx & 127;
    int n = n0 + e; if (n >= N) n = 0;
    xs_rT[s * 16 + e] = (s < 64) ? __ldg(node_s + (size_t)n * 64 + s)
                                 : g_agg_s[(size_t)n * 64 + (s - 64)];
  }
  for (int idx = tid; idx < TE * 384; idx += 128) {
    int e = idx / 384, j = idx - e * 384;
    int n = n0 + e; if (n >= N) n = 0;
    float v = (j < 192) ? __ldg(node_v + (size_t)n * 192 + j)
                        : g_agg_v[(size_t)n * 192 + (j - 192)];
    xvT[j * 16 + e] = v;
  }
  __syncthreads();

  for (int t = tid; t < TE * 128; t += 128) {
    int v = t >> 4, e = t & 15;
    d1T[v * 16 + e] = (xvT[(v * 3 + 0) * 16 + e] * avx[e] +
                       xvT[(v * 3 + 1) * 16 + e] * avx[16 + e] +
                       xvT[(v * 3 + 2) * 16 + e] * avx[32 + e]) * RSQRT3;
  }
  __syncthreads();

  // ---- u0 scalar ----
  {
    const int grp = tid >> 6;
    const int o2 = tid & 63;
    float* exch = hvT;
    ull accA[8] = {0,0,0,0,0,0,0,0}, accB[8] = {0,0,0,0,0,0,0,0};
    if (grp == 0) {
      gemmR2<128, 128, 16>(Wss0, o2, xs_rT, accA, accB);
    } else {
      gemmR2<128, 128, 16>(Wvs0, o2, d1T, accA, accB);
      float pa[16], pb[16]; upk16(accA, pa); upk16(accB, pb);
#pragma unroll
      for (int e = 0; e < TE; e++) {
        exch[(2 * o2) * 16 + e] = pa[e];
        exch[(2 * o2 + 1) * 16 + e] = pb[e];
      }
    }
    __syncthreads();
    if (grp == 0) {
      float pa[16], pb[16]; upk16(accA, pa); upk16(accB, pb);
      int oA = 2 * o2, oB = 2 * o2 + 1;
      float bA = __ldg(b0 + oA), bB = __ldg(b0 + oB);
      if (oA < 64) {
#pragma unroll
        for (int e = 0; e < TE; e++) {
          float a = asx[e];
          float s1 = (a * pa[e] + exch[oA * 16 + e]) * INV0 + bA;
          hs_rT[oA * 16 + e] = s1 * sigm(s1);
          float s2 = (a * pb[e] + exch[oB * 16 + e]) * INV0 + bB;
          hs_rT[oB * 16 + e] = s2 * sigm(s2);
        }
      } else {
#pragma unroll
        for (int e = 0; e < TE; e++) {
          float a = asx[e];
          gT[(oA - 64) * 16 + e] = sigm((a * pa[e] + exch[oA * 16 + e]) * INV0 + bA);
          gT[(oB - 64) * 16 + e] = sigm((a * pb[e] + exch[oB * 16 + e]) * INV0 + bB);
        }
      }
    }
  }
  __syncthreads();

  // ---- u0 vector ----
  {
    const int role = tid >> 5;
    const int o2 = tid & 31;
    ull accA[8] = {0,0,0,0,0,0,0,0}, accB[8] = {0,0,0,0,0,0,0,0};
    if (role < 3) {
      gemmR2<128, 64, 48>(Wvv0, o2, xvT + role * 16, accA, accB);
    } else {
      gemmR2<128, 64, 16>(Wsv0, o2, xs_rT, accA, accB);
      float pa[16], pb[16]; upk16(accA, pa); upk16(accB, pb);
#pragma unroll
      for (int e = 0; e < TE; e++) {
        pT[(2 * o2) * 16 + e] = pa[e];
        pT[(2 * o2 + 1) * 16 + e] = pb[e];
      }
    }
    __syncthreads();
    if (role < 3) {
      float qa[16], qb[16]; upk16(accA, qa); upk16(accB, qb);
      int oA = 2 * o2, oB = 2 * o2 + 1;
#pragma unroll
      for (int e = 0; e < TE; e++) {
        float a = asx[e];
        hvT[(oA * 3 + role) * 16 + e] =
            (pT[oA * 16 + e] * avx[role * 16 + e] + a * qa[e]) * gT[oA * 16 + e] * INV0;
        hvT[(oB * 3 + role) * 16 + e] =
            (pT[oB * 16 + e] * avx[role * 16 + e] + a * qb[e]) * gT[oB * 16 + e] * INV0;
      }
    }
  }
  __syncthreads();

  for (int t = tid; t < TE * 64; t += 128) {
    int v = t >> 4, e = t & 15;
    d2T[v * 16 + e] = (hvT[(v * 3 + 0) * 16 + e] * avx[e] +
                       hvT[(v * 3 + 1) * 16 + e] * avx[16 + e] +
                       hvT[(v * 3 + 2) * 16 + e] * avx[32 + e]) * RSQRT3;
  }
  __syncthreads();

  // ---- u1 scalar: role0 Wssu, role1 Wvsu -> exchange (gT) ----
  {
    const int role = tid >> 5;
    const int o2 = tid & 31;
    float* exch = gT;
    ull accA[8] = {0,0,0,0,0,0,0,0}, accB[8] = {0,0,0,0,0,0,0,0};
    if (role == 1) {
      gemmR2<64, 64, 16>(Wvsu, o2, d2T, accA, accB);
      float pa[16], pb[16]; upk16(accA, pa); upk16(accB, pb);
#pragma unroll
      for (int e = 0; e < TE; e++) {
        exch[(2 * o2) * 16 + e] = pa[e];
        exch[(2 * o2 + 1) * 16 + e] = pb[e];
      }
    } else if (role == 0) {
      gemmR2<64, 64, 16>(Wssu, o2, hs_rT, accA, accB);
    }
    __syncthreads();
    if (role == 0) {
      float pa[16], pb[16]; upk16(accA, pa); upk16(accB, pb);
      int oA = 2 * o2, oB = 2 * o2 + 1;
      float bA = __ldg(bu + oA), bB = __ldg(bu + oB);
#pragma unroll
      for (int e = 0; e < TE; e++) {
        int n = n0 + e;
        if (n >= N) continue;
        float a = asx[e];
        out[(size_t)n * 256 + oA] =
            __ldg(node_s + (size_t)n * 64 + oA) + (a * pa[e] + exch[oA * 16 + e]) * INVU + bA;
        out[(size_t)n * 256 + oB] =
            __ldg(node_s + (size_t)n * 64 + oB) + (a * pb[e] + exch[oB * 16 + e]) * INVU + bB;
      }
    }
  }
  __syncthreads();

  // ---- u1 vector: 4 roles x 32 x pair; residual writes ----
  {
    const int role = tid >> 5;
    const int o2 = tid & 31;
    ull accA[8] = {0,0,0,0,0,0,0,0}, accB[8] = {0,0,0,0,0,0,0,0};
    if (role < 3) {
      gemmR2<64, 64, 48>(Wvvu, o2, hvT + role * 16, accA, accB);
    } else {
      gemmR2<64, 64, 16>(Wsvu, o2, hs_rT, accA, accB);
      float pa[16], pb[16]; upk16(accA, pa); upk16(accB, pb);
#pragma unroll
      for (int e = 0; e < TE; e++) {
        pT[(2 * o2) * 16 + e] = pa[e];
        pT[(2 * o2 + 1) * 16 + e] = pb[e];
      }
    }
    __syncthreads();
    if (role < 3) {
      float qa[16], qb[16]; upk16(accA, qa); upk16(accB, qb);
      int oA = 2 * o2, oB = 2 * o2 + 1;
#pragma unroll
      for (int e = 0; e < TE; e++) {
        int n = n0 + e;
        if (n >= N) continue;
        float a = asx[e];
        out[(size_t)n * 256 + 64 + oA * 3 + role] =
            __ldg(node_v + (size_t)n * 192 + oA * 3 + role) +
            (pT[oA * 16 + e] * avx[role * 16 + e] + a * qa[e]) * INVU;
        out[(size_t)n * 256 + 64 + oB * 3 + role] =
            __ldg(node_v + (size_t)n * 192 + oB * 3 + role) +
            (pT[oB * 16 + e] * avx[role * 16 + e] + a * qb[e]) * INVU;
      }
    }
  }
}

extern "C" void kernel_launch(void* const* d_in, const int* in_sizes, int n_in,
                              void* d_out, int out_size) {
  const float* node_s = (const float*)d_in[0];
  const float* node_v = (const float*)d_in[1];
  const float* nas    = (const float*)d_in[2];
  const float* nav    = (const float*)d_in[3];
  const float* eas    = (const float*)d_in[4];
  const float* eav    = (const float*)d_in[5];
  const float* add_f  = (const float*)d_in[6];
  const float* m1Wss  = (const float*)d_in[7];
  const float* m1Wvs  = (const float*)d_in[8];
  const float* m1Wsv  = (const float*)d_in[9];
  const float* m1Wvv  = (const float*)d_in[10];
  const float* m1b    = (const float*)d_in[11];
  const float* m2Wss  = (const float*)d_in[12];
  const float* m2Wvs  = (const float*)d_in[13];
  const float* m2Wsv  = (const float*)d_in[14];
  const float* m2Wvv  = (const float*)d_in[15];
  const float* m2b    = (const float*)d_in[16];
  const float* u0Wss  = (const float*)d_in[17];
  const float* u0Wvs  = (const float*)d_in[18];
  const float* u0Wsv  = (const float*)d_in[19];
  const float* u0Wvv  = (const float*)d_in[20];
  const float* u0b    = (const float*)d_in[21];
  const float* u1Wss  = (const float*)d_in[22];
  const float* u1Wvs  = (const float*)d_in[23];
  const float* u1Wsv  = (const float*)d_in[24];
  const float* u1Wvv  = (const float*)d_in[25];
  const float* u1b    = (const float*)d_in[26];
  const int* senders   = (const int*)d_in[27];
  const int* receivers = (const int*)d_in[28];

  int E = in_sizes[27];
  int N = in_sizes[0] / 64;

  cudaFuncSetAttribute(edge_kernel, cudaFuncAttributeMaxDynamicSharedMemorySize,
                       EDGE_SMEM_BYTES);
  cudaFuncSetAttribute(node_kernel, cudaFuncAttributeMaxDynamicSharedMemorySize,
                       NODE_SMEM_BYTES);

  void* p_s = nullptr; void* p_v = nullptr;
  cudaGetSymbolAddress(&p_s, g_agg_s);
  cudaGetSymbolAddress(&p_v, g_agg_v);
  cudaMemsetAsync(p_s, 0, (size_t)N * 64 * sizeof(float));
  cudaMemsetAsync(p_v, 0, (size_t)N * 192 * sizeof(float));

  edge_kernel<<<(E + TE - 1) / TE, 128, EDGE_SMEM_BYTES>>>(
      node_s, node_v, eas, eav, add_f,
      m1Wss, m1Wvs, m1Wsv, m1Wvv, m1b,
      m2Wss, m2Wvs, m2Wsv, m2Wvv, m2b,
      senders, receivers, E);
  node_kernel<<<(N + TE - 1) / TE, 128, NODE_SMEM_BYTES>>>(
      node_s, node_v, nas, nav,
      u0Wss, u0Wvs, u0Wsv, u0Wvv, u0b,
      u1Wss, u1Wvs, u1Wsv, u1Wvv, u1b,
      (float*)d_out, N);
}

// round 12
// speedup vs baseline: 1.4680x; 1.4680x over previous
#include <cuda_runtime.h>

#define TE 8
#define NODES_MAX 50000

typedef unsigned long long ull;

__device__ float g_agg_s[(size_t)NODES_MAX * 64];
__device__ float g_agg_v[(size_t)NODES_MAX * 192];
// per-node m1 precompute: [n][1536] =
//  A-half (sender role):  SA[128] @0, PA[64] @128, TA[3][128] @192, QA[3][64] @576
//  B-half (receiver role): same layout @768
__device__ float g_pre[(size_t)NODES_MAX * 1536];

__device__ __forceinline__ ull ffma2(ull a, ull b, ull c) {
  ull d;
  asm("fma.rn.f32x2 %0, %1, %2, %3;" : "=l"(d) : "l"(a), "l"(b), "l"(c));
  return d;
}
__device__ __forceinline__ ull pack2(float x) {
  ull d;
  asm("mov.b64 %0, {%1, %1};" : "=l"(d) : "f"(x));
  return d;
}
__device__ __forceinline__ void upk8(const ull* a, float* f) {
#pragma unroll
  for (int j = 0; j < 4; j++) {
    f[2 * j]     = __int_as_float((int)(unsigned)(a[j] & 0xffffffffull));
    f[2 * j + 1] = __int_as_float((int)(unsigned)(a[j] >> 32));
  }
}
__device__ __forceinline__ float sigm(float x) { return 1.0f / (1.0f + __expf(-x)); }

#define RSQRT3 0.5773502692f
#define INV1   0.0622573010f   // 1/sqrt(258)
#define INV2   0.0883883476f   // 1/sqrt(128)
#define INV0   0.0625f         // 1/sqrt(256)
#define INVU   0.0883883476f   // 1/sqrt(128)

#define ACC4W2(arrRow, wa, wb, A, B) do {                                      \
    ulonglong2 _r0 = *reinterpret_cast<const ulonglong2*>(arrRow);             \
    ulonglong2 _r1 = *reinterpret_cast<const ulonglong2*>((arrRow) + 4);       \
    (A)[0] = ffma2(_r0.x, (wa), (A)[0]);                                       \
    (B)[0] = ffma2(_r0.x, (wb), (B)[0]);                                       \
    (A)[1] = ffma2(_r0.y, (wa), (A)[1]);                                       \
    (B)[1] = ffma2(_r0.y, (wb), (B)[1]);                                       \
    (A)[2] = ffma2(_r1.x, (wa), (A)[2]);                                       \
    (B)[2] = ffma2(_r1.x, (wb), (B)[2]);                                       \
    (A)[3] = ffma2(_r1.y, (wa), (A)[3]);                                       \
    (B)[3] = ffma2(_r1.y, (wb), (B)[3]);                                       \
  } while (0)

// R=2 GEMM over 8 edges/nodes: outputs (2*o2, 2*o2+1); one LDG.64 per k.
template <int K, int LDW, int RS>
__device__ __forceinline__ void gemmR2(const float* __restrict__ W, int o2,
                                       const float* __restrict__ row,
                                       ull* accA, ull* accB) {
#pragma unroll 1
  for (int k0 = 0; k0 < K; k0 += 4) {
    float2 w[4];
#pragma unroll
    for (int j = 0; j < 4; j++)
      w[j] = __ldg(reinterpret_cast<const float2*>(W + (size_t)(k0 + j) * LDW) + o2);
#pragma unroll
    for (int j = 0; j < 4; j++) {
      ull wa = pack2(w[j].x), wb = pack2(w[j].y);
      ACC4W2(row + (size_t)(k0 + j) * RS, wa, wb, accA, accB);
    }
  }
}

// ---------------------------------------------------------------------------
// Precompute kernel: per-node m1 partials (8 nodes/CTA, 128 threads).
// ---------------------------------------------------------------------------
__global__ void __launch_bounds__(128, 5) pre_kernel(
    const float* __restrict__ node_s, const float* __restrict__ node_v,
    const float* __restrict__ Wss1, const float* __restrict__ Wvs1,
    const float* __restrict__ Wsv1, const float* __restrict__ Wvv1,
    int N)
{
  __shared__ __align__(16) float nsT[64][TE];
  __shared__ __align__(16) float nvT[64][3][TE];

  const int tid = threadIdx.x;
  const int n0 = blockIdx.x * TE;

  for (int idx = tid; idx < TE * 64; idx += 128) {
    int e = idx >> 6, s = idx & 63;
    int n = n0 + e; if (n >= N) n = 0;
    nsT[s][e] = __ldg(node_s + (size_t)n * 64 + s);
  }
  for (int idx = tid; idx < TE * 192; idx += 128) {
    int e = idx / 192, j = idx - e * 192;
    int n = n0 + e; if (n >= N) n = 0;
    nvT[j / 3][j % 3][e] = __ldg(node_v + (size_t)n * 192 + j);
  }
  __syncthreads();

  // helper to store a pair of output columns for all 8 nodes
  auto store2 = [&](int base, int oA, const float* pa, const float* pb) {
#pragma unroll
    for (int e = 0; e < TE; e++) {
      int n = n0 + e;
      if (n >= N) continue;
      g_pre[(size_t)n * 1536 + base + oA] = pa[e];
      g_pre[(size_t)n * 1536 + base + oA + 1] = pb[e];
    }
  };

  // Ph1: SA (grp0) / SB (grp1): ns @ Wss1 rows [0,64) / [64,128); 128 outs
  {
    const int grp = tid >> 6, o2 = tid & 63;
    ull accA[4] = {0,0,0,0}, accB[4] = {0,0,0,0};
    gemmR2<64, 128, TE>(Wss1 + (size_t)(grp ? 64 : 0) * 128, o2, &nsT[0][0], accA, accB);
    float pa[8], pb[8]; upk8(accA, pa); upk8(accB, pb);
    store2(grp ? 768 : 0, 2 * o2, pa, pb);
  }
  // Ph2-4: T_i = nv_i @ Wvs1 rows [0,64)/[64,128); 128 outs each comp
#pragma unroll 1
  for (int i = 0; i < 3; i++) {
    const int grp = tid >> 6, o2 = tid & 63;
    ull accA[4] = {0,0,0,0}, accB[4] = {0,0,0,0};
    gemmR2<64, 128, 3 * TE>(Wvs1 + (size_t)(grp ? 64 : 0) * 128, o2, &nvT[0][i][0],
                            accA, accB);
    float pa[8], pb[8]; upk8(accA, pa); upk8(accB, pb);
    store2((grp ? 768 : 0) + 192 + i * 128, 2 * o2, pa, pb);
  }
  // Ph5: role0=PA, role1=PB (ns@Wsv1 halves); role2=QA0, role3=QB0
  {
    const int role = tid >> 5, o2 = tid & 31;
    ull accA[4] = {0,0,0,0}, accB[4] = {0,0,0,0};
    if (role < 2) {
      gemmR2<64, 64, TE>(Wsv1 + (size_t)(role ? 64 : 0) * 64, o2, &nsT[0][0], accA, accB);
      float pa[8], pb[8]; upk8(accA, pa); upk8(accB, pb);
      store2((role ? 768 : 0) + 128, 2 * o2, pa, pb);
    } else {
      gemmR2<64, 64, 3 * TE>(Wvv1 + (size_t)(role == 3 ? 64 : 0) * 64, o2,
                             &nvT[0][0][0], accA, accB);
      float pa[8], pb[8]; upk8(accA, pa); upk8(accB, pb);
      store2((role == 3 ? 768 : 0) + 576, 2 * o2, pa, pb);
    }
  }
  // Ph6: QA1, QB1, QA2, QB2
  {
    const int role = tid >> 5, o2 = tid & 31;
    const int i = 1 + (role >> 1);      // 1,1,2,2
    const int half = role & 1;          // A,B,A,B
    ull accA[4] = {0,0,0,0}, accB[4] = {0,0,0,0};
    gemmR2<64, 64, 3 * TE>(Wvv1 + (size_t)(half ? 64 : 0) * 64, o2, &nvT[0][i][0],
                           accA, accB);
    float pa[8], pb[8]; upk8(accA, pa); upk8(accB, pb);
    store2((half ? 768 : 0) + 576 + i * 64, 2 * o2, pa, pb);
  }
}

// ---------------------------------------------------------------------------
// Edge kernel: gather-combine precomputed m1 + m2 GEMMs + atomic scatter.
// ---------------------------------------------------------------------------
__global__ void __launch_bounds__(128, 5) edge_kernel(
    const float* __restrict__ eas, const float* __restrict__ eav,
    const float* __restrict__ add_feat,
    const float* __restrict__ Wss1, const float* __restrict__ Wsv1,
    const float* __restrict__ b1,
    const float* __restrict__ Wss2, const float* __restrict__ Wvs2,
    const float* __restrict__ Wsv2, const float* __restrict__ Wvv2,
    const float* __restrict__ b2,
    const int* __restrict__ senders, const int* __restrict__ receivers,
    int E)
{
  __shared__ __align__(16) float Sg[128][TE];      // SA[snd]+SB[rcv]
  __shared__ __align__(16) float Pg[64][TE];       // PA+PB
  __shared__ __align__(16) float Tg[3][128][TE];   // TA+TB; later m2 exchange
  __shared__ __align__(16) float Qg[3][64][TE];    // QA+QB
  __shared__ __align__(16) float ms_rT[64][TE];
  __shared__ __align__(16) float gT[64][TE];
  __shared__ __align__(16) float d2T[64][TE];
  __shared__ __align__(16) float mvT[64][3][TE];
  __shared__ __align__(16) float pT[64][TE];
  __shared__ float asx[TE], avx[3][TE], afx[2][TE];
  __shared__ int sndx[TE], rcvx[TE];

  const int tid = threadIdx.x;
  const int e0 = blockIdx.x * TE;

  if (tid < TE) {
    int ge = e0 + tid;
    bool val = ge < E;
    sndx[tid] = val ? senders[ge] : 0;
    rcvx[tid] = val ? receivers[ge] : -1;
    asx[tid]  = val ? eas[ge] : 0.f;
#pragma unroll
    for (int i = 0; i < 3; i++) avx[i][tid] = val ? eav[ge * 3 + i] : 0.f;
#pragma unroll
    for (int i = 0; i < 2; i++) afx[i][tid] = val ? add_feat[(size_t)ge * 2 + i] : 0.f;
  }
  __syncthreads();

  // gather + combine precomputed halves: v = preA[snd][f] + preB[rcv][f]
  for (int idx = tid; idx < TE * 768; idx += 128) {
    int e = idx / 768, f = idx - e * 768;
    int r = rcvx[e] < 0 ? 0 : rcvx[e];
    float v = __ldg(g_pre + (size_t)sndx[e] * 1536 + f) +
              __ldg(g_pre + (size_t)r * 1536 + 768 + f);
    if (f < 128)      Sg[f][e] = v;
    else if (f < 192) Pg[f - 128][e] = v;
    else if (f < 576) { int t = f - 192; Tg[t >> 7][t & 127][e] = v; }
    else              { int t = f - 576; Qg[t / 64][t % 64][e] = v; }
  }
  __syncthreads();

  // ---- m1 scalar combine (o = tid) ----
  {
    const int o = tid;
    float w128 = __ldg(Wss1 + (size_t)128 * 128 + o);
    float w129 = __ldg(Wss1 + (size_t)129 * 128 + o);
    float bo = __ldg(b1 + o);
    if (o < 64) {
#pragma unroll
      for (int e = 0; e < TE; e++) {
        float ss = Sg[o][e] + afx[0][e] * w128 + afx[1][e] * w129;
        float vs = (avx[0][e] * Tg[0][o][e] + avx[1][e] * Tg[1][o][e] +
                    avx[2][e] * Tg[2][o][e]) * RSQRT3;
        float s1 = (asx[e] * ss + vs) * INV1 + bo;
        ms_rT[o][e] = s1 * sigm(s1);
      }
    } else {
#pragma unroll
      for (int e = 0; e < TE; e++) {
        float ss = Sg[o][e] + afx[0][e] * w128 + afx[1][e] * w129;
        float vs = (avx[0][e] * Tg[0][o][e] + avx[1][e] * Tg[1][o][e] +
                    avx[2][e] * Tg[2][o][e]) * RSQRT3;
        gT[o - 64][e] = sigm((asx[e] * ss + vs) * INV1 + bo);
      }
    }
  }
  __syncthreads();

  // ---- m1 vector combine (threads 0-63) ----
  if (tid < 64) {
    const int o = tid;
    float v128 = __ldg(Wsv1 + (size_t)128 * 64 + o);
    float v129 = __ldg(Wsv1 + (size_t)129 * 64 + o);
#pragma unroll
    for (int e = 0; e < TE; e++) {
      float p = Pg[o][e] + afx[0][e] * v128 + afx[1][e] * v129;
      float gi = gT[o][e] * INV1;
      float a = asx[e];
      mvT[o][0][e] = (p * avx[0][e] + a * Qg[0][o][e]) * gi;
      mvT[o][1][e] = (p * avx[1][e] + a * Qg[1][o][e]) * gi;
      mvT[o][2][e] = (p * avx[2][e] + a * Qg[2][o][e]) * gi;
    }
  }
  __syncthreads();

  // d2 = (mv . av)/sqrt3
  for (int t = tid; t < TE * 64; t += 128) {
    int v = t >> 3, e = t & 7;
    d2T[v][e] = (mvT[v][0][e] * avx[0][e] + mvT[v][1][e] * avx[1][e] +
                 mvT[v][2][e] * avx[2][e]) * RSQRT3;
  }
  __syncthreads();

  // ---- m2 scalar (split GEMM, exchange via Tg) ----
  {
    const int grp = tid >> 6;
    const int o2 = tid & 63;
    float* exch = &Tg[0][0][0];
    ull accA[4] = {0,0,0,0}, accB[4] = {0,0,0,0};
    if (grp == 0) {
      gemmR2<64, 128, TE>(Wss2, o2, &ms_rT[0][0], accA, accB);
    } else {
      gemmR2<64, 128, TE>(Wvs2, o2, &d2T[0][0], accA, accB);
      float pa[8], pb[8]; upk8(accA, pa); upk8(accB, pb);
#pragma unroll
      for (int e = 0; e < TE; e++) {
        exch[(2 * o2) * TE + e] = pa[e];
        exch[(2 * o2 + 1) * TE + e] = pb[e];
      }
    }
    __syncthreads();
    if (grp == 0) {
      float pa[8], pb[8]; upk8(accA, pa); upk8(accB, pb);
      int oA = 2 * o2, oB = 2 * o2 + 1;
      float bA = __ldg(b2 + oA), bB = __ldg(b2 + oB);
      if (oA < 64) {
#pragma unroll
        for (int e = 0; e < TE; e++) {
          int r = rcvx[e];
          if (r < 0) continue;
          float a = asx[e];
          float s1 = (a * pa[e] + exch[oA * TE + e]) * INV2 + bA;
          float s2 = (a * pb[e] + exch[oB * TE + e]) * INV2 + bB;
          atomicAdd(g_agg_s + (size_t)r * 64 + oA, s1 * sigm(s1));
          atomicAdd(g_agg_s + (size_t)r * 64 + oB, s2 * sigm(s2));
        }
      } else {
#pragma unroll
        for (int e = 0; e < TE; e++) {
          float a = asx[e];
          gT[oA - 64][e] = sigm((a * pa[e] + exch[oA * TE + e]) * INV2 + bA);
          gT[oB - 64][e] = sigm((a * pb[e] + exch[oB * TE + e]) * INV2 + bB);
        }
      }
    }
  }
  __syncthreads();

  // ---- m2 vector (4 roles x 32 x pair) + atomic scatter ----
  {
    const int role = tid >> 5;
    const int o2 = tid & 31;
    ull accA[4] = {0,0,0,0}, accB[4] = {0,0,0,0};
    if (role < 3) {
      gemmR2<64, 64, 3 * TE>(Wvv2, o2, &mvT[0][role][0], accA, accB);
    } else {
      gemmR2<64, 64, TE>(Wsv2, o2, &ms_rT[0][0], accA, accB);
      float pa[8], pb[8]; upk8(accA, pa); upk8(accB, pb);
#pragma unroll
      for (int e = 0; e < TE; e++) {
        pT[2 * o2][e] = pa[e];
        pT[2 * o2 + 1][e] = pb[e];
      }
    }
    __syncthreads();
    if (role < 3) {
      float qa[8], qb[8]; upk8(accA, qa); upk8(accB, qb);
      int oA = 2 * o2, oB = 2 * o2 + 1;
#pragma unroll
      for (int e = 0; e < TE; e++) {
        int r = rcvx[e];
        if (r < 0) continue;
        float a = asx[e];
        atomicAdd(g_agg_v + (size_t)r * 192 + oA * 3 + role,
                  (pT[oA][e] * avx[role][e] + a * qa[e]) * gT[oA][e] * INV2);
        atomicAdd(g_agg_v + (size_t)r * 192 + oB * 3 + role,
                  (pT[oB][e] * avx[role][e] + a * qb[e]) * gT[oB][e] * INV2);
      }
    }
  }
}

// ---------------------------------------------------------------------------
// Node kernel: identical to R9 winner.
// ---------------------------------------------------------------------------
__global__ void __launch_bounds__(128, 6) node_kernel(
    const float* __restrict__ node_s, const float* __restrict__ node_v,
    const float* __restrict__ nas, const float* __restrict__ nav,
    const float* __restrict__ Wss0, const float* __restrict__ Wvs0,
    const float* __restrict__ Wsv0, const float* __restrict__ Wvv0,
    const float* __restrict__ b0,
    const float* __restrict__ Wssu, const float* __restrict__ Wvsu,
    const float* __restrict__ Wsvu, const float* __restrict__ Wvvu,
    const float* __restrict__ bu,
    float* __restrict__ out, int N)
{
  __shared__ __align__(16) float xs_rT[128][TE];
  __shared__ __align__(16) float d1T[128][TE];
  __shared__ __align__(16) float xvT[128][3][TE];
  __shared__ __align__(16) float hs_rT[64][TE];
  __shared__ __align__(16) float gT[64][TE];
  __shared__ __align__(16) float d2T[64][TE];
  __shared__ __align__(16) float hvT[64][3][TE];
  __shared__ __align__(16) float pT[64][TE];
  __shared__ float asx[TE], avx[3][TE];

  const int tid = threadIdx.x;
  const int n0 = blockIdx.x * TE;

  if (tid < TE) {
    int n = n0 + tid;
    bool val = n < N;
    asx[tid] = val ? nas[n] : 0.f;
#pragma unroll
    for (int i = 0; i < 3; i++) avx[i][tid] = val ? nav[n * 3 + i] : 0.f;
  }
  __syncthreads();

  for (int idx = tid; idx < TE * 128; idx += 128) {
    int e = idx >> 7, s = idx & 127;
    int n = n0 + e; if (n >= N) n = 0;
    xs_rT[s][e] = (s < 64) ? __ldg(node_s + (size_t)n * 64 + s)
                           : g_agg_s[(size_t)n * 64 + (s - 64)];
  }
  for (int idx = tid; idx < TE * 384; idx += 128) {
    int e = idx / 384, j = idx - e * 384;
    int n = n0 + e; if (n >= N) n = 0;
    float v = (j < 192) ? __ldg(node_v + (size_t)n * 192 + j)
                        : g_agg_v[(size_t)n * 192 + (j - 192)];
    xvT[j / 3][j % 3][e] = v;
  }
  __syncthreads();

  for (int t = tid; t < TE * 128; t += 128) {
    int v = t >> 3, e = t & 7;
    d1T[v][e] = (xvT[v][0][e] * avx[0][e] + xvT[v][1][e] * avx[1][e] +
                 xvT[v][2][e] * avx[2][e]) * RSQRT3;
  }
  __syncthreads();

  // ---- u0 scalar ----
  {
    const int grp = tid >> 6;
    const int o2 = tid & 63;
    float* exch = &hvT[0][0][0];
    ull accA[4] = {0,0,0,0}, accB[4] = {0,0,0,0};
    if (grp == 0) {
      gemmR2<128, 128, TE>(Wss0, o2, &xs_rT[0][0], accA, accB);
    } else {
      gemmR2<128, 128, TE>(Wvs0, o2, &d1T[0][0], accA, accB);
      float pa[8], pb[8]; upk8(accA, pa); upk8(accB, pb);
#pragma unroll
      for (int e = 0; e < TE; e++) {
        exch[(2 * o2) * TE + e] = pa[e];
        exch[(2 * o2 + 1) * TE + e] = pb[e];
      }
    }
    __syncthreads();
    if (grp == 0) {
      float pa[8], pb[8]; upk8(accA, pa); upk8(accB, pb);
      int oA = 2 * o2, oB = 2 * o2 + 1;
      float bA = __ldg(b0 + oA), bB = __ldg(b0 + oB);
      if (oA < 64) {
#pragma unroll
        for (int e = 0; e < TE; e++) {
          float a = asx[e];
          float s1 = (a * pa[e] + exch[oA * TE + e]) * INV0 + bA;
          hs_rT[oA][e] = s1 * sigm(s1);
          float s2 = (a * pb[e] + exch[oB * TE + e]) * INV0 + bB;
          hs_rT[oB][e] = s2 * sigm(s2);
        }
      } else {
#pragma unroll
        for (int e = 0; e < TE; e++) {
          float a = asx[e];
          gT[oA - 64][e] = sigm((a * pa[e] + exch[oA * TE + e]) * INV0 + bA);
          gT[oB - 64][e] = sigm((a * pb[e] + exch[oB * TE + e]) * INV0 + bB);
        }
      }
    }
  }
  __syncthreads();

  // ---- u0 vector ----
  {
    const int role = tid >> 5;
    const int o2 = tid & 31;
    ull accA[4] = {0,0,0,0}, accB[4] = {0,0,0,0};
    if (role < 3) {
      gemmR2<128, 64, 3 * TE>(Wvv0, o2, &xvT[0][role][0], accA, accB);
    } else {
      gemmR2<128, 64, TE>(Wsv0, o2, &xs_rT[0][0], accA, accB);
      float pa[8], pb[8]; upk8(accA, pa); upk8(accB, pb);
#pragma unroll
      for (int e = 0; e < TE; e++) {
        pT[2 * o2][e] = pa[e];
        pT[2 * o2 + 1][e] = pb[e];
      }
    }
    __syncthreads();
    if (role < 3) {
      float qa[8], qb[8]; upk8(accA, qa); upk8(accB, qb);
      int oA = 2 * o2, oB = 2 * o2 + 1;
#pragma unroll
      for (int e = 0; e < TE; e++) {
        float a = asx[e];
        hvT[oA][role][e] = (pT[oA][e] * avx[role][e] + a * qa[e]) * gT[oA][e] * INV0;
        hvT[oB][role][e] = (pT[oB][e] * avx[role][e] + a * qb[e]) * gT[oB][e] * INV0;
      }
    }
  }
  __syncthreads();

  for (int t = tid; t < TE * 64; t += 128) {
    int v = t >> 3, e = t & 7;
    d2T[v][e] = (hvT[v][0][e] * avx[0][e] + hvT[v][1][e] * avx[1][e] +
                 hvT[v][2][e] * avx[2][e]) * RSQRT3;
  }
  __syncthreads();

  // ---- u1 scalar ----
  {
    const int role = tid >> 5;
    const int o2 = tid & 31;
    float* exch = &gT[0][0];
    ull accA[4] = {0,0,0,0}, accB[4] = {0,0,0,0};
    if (role == 1) {
      gemmR2<64, 64, TE>(Wvsu, o2, &d2T[0][0], accA, accB);
      float pa[8], pb[8]; upk8(accA, pa); upk8(accB, pb);
#pragma unroll
      for (int e = 0; e < TE; e++) {
        exch[(2 * o2) * TE + e] = pa[e];
        exch[(2 * o2 + 1) * TE + e] = pb[e];
      }
    } else if (role == 0) {
      gemmR2<64, 64, TE>(Wssu, o2, &hs_rT[0][0], accA, accB);
    }
    __syncthreads();
    if (role == 0) {
      float pa[8], pb[8]; upk8(accA, pa); upk8(accB, pb);
      int oA = 2 * o2, oB = 2 * o2 + 1;
      float bA = __ldg(bu + oA), bB = __ldg(bu + oB);
#pragma unroll
      for (int e = 0; e < TE; e++) {
        int n = n0 + e;
        if (n >= N) continue;
        float a = asx[e];
        out[(size_t)n * 256 + oA] =
            __ldg(node_s + (size_t)n * 64 + oA) + (a * pa[e] + exch[oA * TE + e]) * INVU + bA;
        out[(size_t)n * 256 + oB] =
            __ldg(node_s + (size_t)n * 64 + oB) + (a * pb[e] + exch[oB * TE + e]) * INVU + bB;
      }
    }
  }
  __syncthreads();

  // ---- u1 vector ----
  {
    const int role = tid >> 5;
    const int o2 = tid & 31;
    ull accA[4] = {0,0,0,0}, accB[4] = {0,0,0,0};
    if (role < 3) {
      gemmR2<64, 64, 3 * TE>(Wvvu, o2, &hvT[0][role][0], accA, accB);
    } else {
      gemmR2<64, 64, TE>(Wsvu, o2, &hs_rT[0][0], accA, accB);
      float pa[8], pb[8]; upk8(accA, pa); upk8(accB, pb);
#pragma unroll
      for (int e = 0; e < TE; e++) {
        pT[2 * o2][e] = pa[e];
        pT[2 * o2 + 1][e] = pb[e];
      }
    }
    __syncthreads();
    if (role < 3) {
      float qa[8], qb[8]; upk8(accA, qa); upk8(accB, qb);
      int oA = 2 * o2, oB = 2 * o2 + 1;
#pragma unroll
      for (int e = 0; e < TE; e++) {
        int n = n0 + e;
        if (n >= N) continue;
        float a = asx[e];
        out[(size_t)n * 256 + 64 + oA * 3 + role] =
            __ldg(node_v + (size_t)n * 192 + oA * 3 + role) +
            (pT[oA][e] * avx[role][e] + a * qa[e]) * INVU;
        out[(size_t)n * 256 + 64 + oB * 3 + role] =
            __ldg(node_v + (size_t)n * 192 + oB * 3 + role) +
            (pT[oB][e] * avx[role][e] + a * qb[e]) * INVU;
      }
    }
  }
}

extern "C" void kernel_launch(void* const* d_in, const int* in_sizes, int n_in,
                              void* d_out, int out_size) {
  const float* node_s = (const float*)d_in[0];
  const float* node_v = (const float*)d_in[1];
  const float* nas    = (const float*)d_in[2];
  const float* nav    = (const float*)d_in[3];
  const float* eas    = (const float*)d_in[4];
  const float* eav    = (const float*)d_in[5];
  const float* add_f  = (const float*)d_in[6];
  const float* m1Wss  = (const float*)d_in[7];
  const float* m1Wvs  = (const float*)d_in[8];
  const float* m1Wsv  = (const float*)d_in[9];
  const float* m1Wvv  = (const float*)d_in[10];
  const float* m1b    = (const float*)d_in[11];
  const float* m2Wss  = (const float*)d_in[12];
  const float* m2Wvs  = (const float*)d_in[13];
  const float* m2Wsv  = (const float*)d_in[14];
  const float* m2Wvv  = (const float*)d_in[15];
  const float* m2b    = (const float*)d_in[16];
  const float* u0Wss  = (const float*)d_in[17];
  const float* u0Wvs  = (const float*)d_in[18];
  const float* u0Wsv  = (const float*)d_in[19];
  const float* u0Wvv  = (const float*)d_in[20];
  const float* u0b    = (const float*)d_in[21];
  const float* u1Wss  = (const float*)d_in[22];
  const float* u1Wvs  = (const float*)d_in[23];
  const float* u1Wsv  = (const float*)d_in[24];
  const float* u1Wvv  = (const float*)d_in[25];
  const float* u1b    = (const float*)d_in[26];
  const int* senders   = (const int*)d_in[27];
  const int* receivers = (const int*)d_in[28];

  int E = in_sizes[27];
  int N = in_sizes[0] / 64;

  void* p_s = nullptr; void* p_v = nullptr;
  cudaGetSymbolAddress(&p_s, g_agg_s);
  cudaGetSymbolAddress(&p_v, g_agg_v);
  cudaMemsetAsync(p_s, 0, (size_t)N * 64 * sizeof(float));
  cudaMemsetAsync(p_v, 0, (size_t)N * 192 * sizeof(float));

  pre_kernel<<<(N + TE - 1) / TE, 128>>>(node_s, node_v, m1Wss, m1Wvs, m1Wsv,
                                         m1Wvv, N);
  edge_kernel<<<(E + TE - 1) / TE, 128>>>(
      eas, eav, add_f,
      m1Wss, m1Wsv, m1b,
      m2Wss, m2Wvs, m2Wsv, m2Wvv, m2b,
      senders, receivers, E);
  node_kernel<<<(N + TE - 1) / TE, 128>>>(
      node_s, node_v, nas, nav,
      u0Wss, u0Wvs, u0Wsv, u0Wvv, u0b,
      u1Wss, u1Wvs, u1Wsv, u1Wvv, u1b,
      (float*)d_out, N);
}